// round 12
// baseline (speedup 1.0000x reference)
#include <cuda_runtime.h>
#include <cuda_fp16.h>
#include <cstdint>
#include <cstddef>

// Shapes fixed by the problem: B=32, S=2048, E=D=1024.
#define BATCH 32
#define SEQ   2048
#define EDIM  1024
#define NROWS (BATCH * SEQ)   // 65536

// ---------------- scratch (static __device__ — no allocation allowed) ----------------
__device__ __half g_Ahi[(size_t)NROWS * EDIM];   // 128 MB  enc hi (fp16)
__device__ __half g_Alo[(size_t)NROWS * EDIM];   // 128 MB  enc lo (fp16)
__device__ __half g_Bh [(size_t)EDIM * EDIM];    // w1^T fp16  [n=e][k=d]
__device__ float g_q[BATCH * EDIM];              // q = dec@w2 + b2 + b1
__device__ float g_scores[NROWS];
__device__ float g_attn[NROWS];

// ---------------- kernel 1: split enc fp32 -> (hi, lo) fp16 ----------------
__global__ void split_enc_kernel(const float* __restrict__ x) {
    const int n4 = NROWS * EDIM / 4;
    for (int idx = blockIdx.x * blockDim.x + threadIdx.x; idx < n4;
         idx += gridDim.x * blockDim.x) {
        float4 v = reinterpret_cast<const float4*>(x)[idx];
        __half h0 = __float2half(v.x);
        __half h1 = __float2half(v.y);
        __half h2 = __float2half(v.z);
        __half h3 = __float2half(v.w);
        __half l0 = __float2half(v.x - __half2float(h0));
        __half l1 = __float2half(v.y - __half2float(h1));
        __half l2 = __float2half(v.z - __half2float(h2));
        __half l3 = __float2half(v.w - __half2float(h3));
        __half2* Hp = reinterpret_cast<__half2*>(g_Ahi) + idx * 2;
        __half2* Lp = reinterpret_cast<__half2*>(g_Alo) + idx * 2;
        Hp[0] = __halves2half2(h0, h1);
        Hp[1] = __halves2half2(h2, h3);
        Lp[0] = __halves2half2(l0, l1);
        Lp[1] = __halves2half2(l2, l3);
    }
}

// ---------------- kernel 2: transpose w1 -> Bh [n][k] fp16 ----------------
__global__ void split_w1_kernel(const float* __restrict__ w1) {
    int idx = blockIdx.x * blockDim.x + threadIdx.x;   // over 1<<20
    int nn = idx >> 10;      // output col e  -> B row
    int kk = idx & 1023;     // input dim d   -> B col
    g_Bh[idx] = __float2half(w1[(kk << 10) + nn]);
}

// ---------------- kernel 3: query projection q[b][e] = dec[b]@w2 + b2 + b1 ----------------
__global__ void query_kernel(const float* __restrict__ dec,
                             const float* __restrict__ w2,
                             const float* __restrict__ b2,
                             const float* __restrict__ b1) {
    const int b = blockIdx.y;
    const int t = threadIdx.x;
    const int e = blockIdx.x * 256 + t;
    __shared__ float sd[EDIM];
    for (int i = t; i < EDIM; i += 256) sd[i] = dec[b * EDIM + i];
    __syncthreads();
    float acc = b2[e] + b1[e];
#pragma unroll 8
    for (int d = 0; d < EDIM; ++d) acc += sd[d] * w2[(d << 10) + e];
    g_q[b * EDIM + e] = acc;
}

// ---------------- kernel 4: pipelined split-fp16 GEMM + fused tanh·v -> scores ----------
#define LDSM4(R0, R1, R2, R3, addr)                                              \
    asm volatile("ldmatrix.sync.aligned.m8n8.x4.shared.b16 {%0,%1,%2,%3}, [%4];" \
                 : "=r"(R0), "=r"(R1), "=r"(R2), "=r"(R3) : "r"(addr))

#define MMA16816(d, a, b0r, b1r)                                                  \
    asm volatile("mma.sync.aligned.m16n8k16.row.col.f32.f16.f16.f32 "             \
                 "{%0,%1,%2,%3}, {%4,%5,%6,%7}, {%8,%9}, {%0,%1,%2,%3};"          \
                 : "+f"((d)[0]), "+f"((d)[1]), "+f"((d)[2]), "+f"((d)[3])         \
                 : "r"((a)[0]), "r"((a)[1]), "r"((a)[2]), "r"((a)[3]),            \
                   "r"(b0r), "r"(b1r))

#define CP_ASYNC16(dst, src)                                                     \
    asm volatile("cp.async.cg.shared.global [%0], [%1], 16;" :: "r"(dst), "l"(src))
#define CP_COMMIT() asm volatile("cp.async.commit_group;" ::: "memory")
#define CP_WAIT2()  asm volatile("cp.async.wait_group 2;" ::: "memory")

// Chunk = (np, k0): tiles {Ahi 128x32h, Alo 128x32h, B 128x32h}, 64B rows, SW64 swizzle.
// 4-stage ring: stage = 3 * 8192 = 24576 B.  256 chunks = 8 np * 32 k-chunks.
// Swizzle: phys = off ^ ((off>>3)&0x30)  (granule g -> g ^ ((row>>1)&3))
#define TILE_BYTES 8192
#define STG_BYTES  24576
#define OFF_Q   98304
#define OFF_V   102400
#define OFF_ACC 106496
#define SMEM_TOTAL 107008

__global__ void __launch_bounds__(256, 2) scores_kernel(const float* __restrict__ v) {
    extern __shared__ char smem[];
    uint32_t sb;
    asm("{ .reg .u64 t; cvta.to.shared.u64 t, %1; cvt.u32.u64 %0, t; }"
        : "=r"(sb) : "l"(smem));

    const int tid  = threadIdx.x;
    const int lane = tid & 31;
    const int wid  = tid >> 5;
    const int wm   = wid >> 1;   // 0..3
    const int wn   = wid & 1;    // 0..1
    const int row0 = blockIdx.x << 7;
    const int b    = row0 >> 11;

    float* s_q   = reinterpret_cast<float*>(smem + OFF_Q);
    float* s_v   = reinterpret_cast<float*>(smem + OFF_V);
    float* s_acc = reinterpret_cast<float*>(smem + OFF_ACC);

    for (int i = tid; i < EDIM; i += 256) {
        s_q[i] = g_q[(b << 10) + i];
        s_v[i] = v[i];
    }
    if (tid < 128) s_acc[tid] = 0.0f;

    // ---- ldmatrix addresses (SW64 swizzled, per-thread constants) ----
    // A: row = wm*32 + (lane&15), logical granule ga = lane>>4 (+2 per kk)
    const int row_a = wm * 32 + (lane & 15);
    const int ga    = lane >> 4;
    const int xa    = (row_a >> 1) & 3;
    const uint32_t a_k0 = (uint32_t)(row_a * 64 + ((ga ^ xa) << 4));
    const uint32_t a_k1 = (uint32_t)(row_a * 64 + (((ga + 2) ^ xa) << 4));
    // B: row = wn*64 + ((lane>>4)<<3) + (lane&7) (+16 per p), granule gb = (lane>>3)&1
    const int row_b = wn * 64 + ((lane >> 4) << 3) + (lane & 7);
    const int gb    = (lane >> 3) & 1;
    const int xb    = (row_b >> 1) & 3;
    const uint32_t b_k0 = (uint32_t)(row_b * 64 + ((gb ^ xb) << 4));
    const uint32_t b_k1 = (uint32_t)(row_b * 64 + (((gb + 2) ^ xb) << 4));

    // ---- staging slots: thread handles slots tid and tid+256 of each 512-slot tile ----
    const int sr0 = tid >> 2, sg0 = tid & 3;
    const uint32_t d0 = (uint32_t)(sr0 * 64 + ((sg0 ^ ((sr0 >> 1) & 3)) << 4));
    // slot tid+256: row += 64, same granule, same xor ((row>>1)&3 unchanged mod 4)
    const uint32_t d1 = d0 + 4096;
    const size_t arow0 = ((size_t)(row0 + sr0)) << 10;          // halves
    const size_t arow1 = arow0 + (size_t)(64 << 10);

    auto stage = [&](int it) {
        const int np = it >> 5;
        const int k0 = (it & 31) << 5;        // halves
        const uint32_t base = sb + (uint32_t)(it & 3) * STG_BYTES;
        const size_t brow0 = (((size_t)((np << 7) + sr0)) << 10);
        CP_ASYNC16(base + d0,                    g_Ahi + arow0 + k0 + sg0 * 8);
        CP_ASYNC16(base + d1,                    g_Ahi + arow1 + k0 + sg0 * 8);
        CP_ASYNC16(base + TILE_BYTES + d0,       g_Alo + arow0 + k0 + sg0 * 8);
        CP_ASYNC16(base + TILE_BYTES + d1,       g_Alo + arow1 + k0 + sg0 * 8);
        CP_ASYNC16(base + 2 * TILE_BYTES + d0,   g_Bh + brow0 + k0 + sg0 * 8);
        CP_ASYNC16(base + 2 * TILE_BYTES + d1,   g_Bh + brow0 + (size_t)(64 << 10) + k0 + sg0 * 8);
    };

    // prologue: prefetch 3 chunks
    stage(0); CP_COMMIT();
    stage(1); CP_COMMIT();
    stage(2); CP_COMMIT();

    float acc[16][4];

#pragma unroll 1
    for (int c = 0; c < 256; ++c) {
        if ((c & 31) == 0) {
#pragma unroll
            for (int i = 0; i < 16; ++i) {
                acc[i][0] = 0.f; acc[i][1] = 0.f; acc[i][2] = 0.f; acc[i][3] = 0.f;
            }
        }

        CP_WAIT2();          // chunk c resident (3 deep)
        __syncthreads();     // all threads' groups arrived; chunk c-1 reads done

        // stage next chunk FIRST so cp.async overlaps the MMA body
        if (c + 3 < 256) stage(c + 3);
        CP_COMMIT();

        const uint32_t base    = sb + (uint32_t)(c & 3) * STG_BYTES;
        const uint32_t ah_base = base;
        const uint32_t al_base = base + TILE_BYTES;
        const uint32_t b_base  = base + 2 * TILE_BYTES;
#pragma unroll
        for (int kk = 0; kk < 2; ++kk) {
            const uint32_t ao = kk ? a_k1 : a_k0;
            const uint32_t bo = kk ? b_k1 : b_k0;
            uint32_t a0h[4], a1h[4], a0l[4], a1l[4];
            LDSM4(a0h[0], a0h[1], a0h[2], a0h[3], ah_base + ao);
            LDSM4(a1h[0], a1h[1], a1h[2], a1h[3], ah_base + ao + 1024);
            LDSM4(a0l[0], a0l[1], a0l[2], a0l[3], al_base + ao);
            LDSM4(a1l[0], a1l[1], a1l[2], a1l[3], al_base + ao + 1024);
#pragma unroll
            for (int p = 0; p < 4; ++p) {
                uint32_t bb0, bb1, bb2, bb3;
                LDSM4(bb0, bb1, bb2, bb3, b_base + bo + p * 1024);
                MMA16816(acc[(p << 1)],         a0h, bb0, bb1);
                MMA16816(acc[(p << 1) + 1],     a0h, bb2, bb3);
                MMA16816(acc[8 + (p << 1)],     a1h, bb0, bb1);
                MMA16816(acc[8 + (p << 1) + 1], a1h, bb2, bb3);
                MMA16816(acc[(p << 1)],         a0l, bb0, bb1);
                MMA16816(acc[(p << 1) + 1],     a0l, bb2, bb3);
                MMA16816(acc[8 + (p << 1)],     a1l, bb0, bb1);
                MMA16816(acc[8 + (p << 1) + 1], a1l, bb2, bb3);
            }
        }

        if ((c & 31) == 31) {
            // epilogue for n-chunk np: score_part[row] += sum_n tanh(C + q) * v
            const int np = c >> 5;
            float part[4] = {0.f, 0.f, 0.f, 0.f};
            const int ncol0 = (np << 7) + wn * 64 + ((lane & 3) << 1);
#pragma unroll
            for (int mf = 0; mf < 2; ++mf) {
#pragma unroll
                for (int nf = 0; nf < 8; ++nf) {
                    int n = ncol0 + (nf << 3);
                    float q0 = s_q[n], q1 = s_q[n + 1];
                    float v0 = s_v[n], v1 = s_v[n + 1];
                    const float* cc = acc[mf * 8 + nf];
                    part[mf * 2 + 0] += tanhf(cc[0] + q0) * v0 + tanhf(cc[1] + q1) * v1;
                    part[mf * 2 + 1] += tanhf(cc[2] + q0) * v0 + tanhf(cc[3] + q1) * v1;
                }
            }
            const int rb = wm * 32 + (lane >> 2);
            atomicAdd(&s_acc[rb],      part[0]);
            atomicAdd(&s_acc[rb + 8],  part[1]);
            atomicAdd(&s_acc[rb + 16], part[2]);
            atomicAdd(&s_acc[rb + 24], part[3]);
        }
    }

    __syncthreads();
    if (tid < 128) g_scores[row0 + tid] = s_acc[tid];   // +bv dropped: softmax-invariant
}

// ---------------- kernel 5: softmax over S per batch ----------------
__global__ void softmax_kernel() {
    const int b = blockIdx.x;
    const int t = threadIdx.x;
    __shared__ float red[256];
    const float* sc = g_scores + b * SEQ;
    float* at = g_attn + b * SEQ;

    float m = -1e30f;
    for (int i = t; i < SEQ; i += 256) m = fmaxf(m, sc[i]);
    red[t] = m; __syncthreads();
#pragma unroll
    for (int o = 128; o > 0; o >>= 1) {
        if (t < o) red[t] = fmaxf(red[t], red[t + o]);
        __syncthreads();
    }
    float mx = red[0];
    __syncthreads();

    float s = 0.f;
    for (int i = t; i < SEQ; i += 256) {
        float e = expf(sc[i] - mx);
        at[i] = e;
        s += e;
    }
    red[t] = s; __syncthreads();
#pragma unroll
    for (int o = 128; o > 0; o >>= 1) {
        if (t < o) red[t] += red[t + o];
        __syncthreads();
    }
    float inv = 1.0f / red[0];
    for (int i = t; i < SEQ; i += 256) at[i] *= inv;
}

// ---------------- kernel 6: context[b][e] = sum_s attn * enc ----------------
__global__ void context_kernel(const float* __restrict__ enc, float* __restrict__ out) {
    const int b = blockIdx.y;
    const int chunk = blockIdx.x;      // 4 chunks of 256 e
    const int t = threadIdx.x;
    const int sub = t >> 6;            // 4 s-partitions
    const int tt = t & 63;

    __shared__ float sa[SEQ];
    __shared__ float4 part[3][64];
    for (int i = t; i < SEQ; i += 256) sa[i] = g_attn[b * SEQ + i];
    __syncthreads();

    const float4* ep = reinterpret_cast<const float4*>(enc) +
                       (size_t)b * SEQ * 256 + chunk * 64 + tt;
    float4 acc = {0.f, 0.f, 0.f, 0.f};
    const int s0 = sub * 512;
#pragma unroll 8
    for (int s = s0; s < s0 + 512; ++s) {
        float a = sa[s];
        float4 x = ep[(size_t)s * 256];
        acc.x += a * x.x; acc.y += a * x.y; acc.z += a * x.z; acc.w += a * x.w;
    }
    if (sub) part[sub - 1][tt] = acc;
    __syncthreads();
    if (sub == 0) {
#pragma unroll
        for (int j = 0; j < 3; ++j) {
            float4 p = part[j][tt];
            acc.x += p.x; acc.y += p.y; acc.z += p.z; acc.w += p.w;
        }
        reinterpret_cast<float4*>(out)[b * 256 + chunk * 64 + tt] = acc;
    }
}

// ---------------- launch ----------------
extern "C" void kernel_launch(void* const* d_in, const int* in_sizes, int n_in,
                              void* d_out, int out_size) {
    const float* enc = (const float*)d_in[0];   // [32,2048,1024]
    const float* dec = (const float*)d_in[1];   // [32,1,1024]
    const float* w1  = (const float*)d_in[2];   // [1024,1024]
    const float* b1  = (const float*)d_in[3];   // [1024]
    const float* w2  = (const float*)d_in[4];   // [1024,1024]
    const float* b2  = (const float*)d_in[5];   // [1024]
    const float* v   = (const float*)d_in[6];   // [1024,1]
    // d_in[7] = bv: softmax-invariant, unused.
    float* out = (float*)d_out;                 // [32,1024]

    cudaFuncSetAttribute(scores_kernel,
                         cudaFuncAttributeMaxDynamicSharedMemorySize, SMEM_TOTAL);

    split_enc_kernel<<<8192, 256>>>(enc);
    split_w1_kernel<<<(EDIM * EDIM) / 256, 256>>>(w1);
    query_kernel<<<dim3(4, BATCH), 256>>>(dec, w2, b2, b1);
    scores_kernel<<<NROWS / 128, 256, SMEM_TOTAL>>>(v);
    softmax_kernel<<<BATCH, 256>>>();
    context_kernel<<<dim3(4, BATCH), 256>>>(enc, out);
}

// round 14
// speedup vs baseline: 1.5909x; 1.5909x over previous
#include <cuda_runtime.h>
#include <cuda_fp16.h>
#include <cstdint>
#include <cstddef>

// Shapes fixed by the problem: B=32, S=2048, E=D=1024.
#define BATCH 32
#define SEQ   2048
#define EDIM  1024
#define NROWS (BATCH * SEQ)   // 65536

// ---------------- scratch (static __device__ — no allocation allowed) ----------------
__device__ __half g_Ah[(size_t)NROWS * EDIM];    // 128 MB  enc fp16
__device__ __half g_Bh[(size_t)EDIM * EDIM];     // w1^T fp16  [n=e][k=d]
__device__ float g_q[BATCH * EDIM];              // q = dec@w2 + b2 + b1
__device__ float g_scores[NROWS];
__device__ float g_attn[NROWS];

// ---------------- kernel 1: convert enc fp32 -> fp16 ----------------
__global__ void conv_enc_kernel(const float* __restrict__ x) {
    const int n4 = NROWS * EDIM / 4;
    for (int idx = blockIdx.x * blockDim.x + threadIdx.x; idx < n4;
         idx += gridDim.x * blockDim.x) {
        float4 v = reinterpret_cast<const float4*>(x)[idx];
        __half2* Hp = reinterpret_cast<__half2*>(g_Ah) + idx * 2;
        Hp[0] = __halves2half2(__float2half(v.x), __float2half(v.y));
        Hp[1] = __halves2half2(__float2half(v.z), __float2half(v.w));
    }
}

// ---------------- kernel 2: transpose w1 -> Bh [n][k] fp16 ----------------
__global__ void conv_w1_kernel(const float* __restrict__ w1) {
    int idx = blockIdx.x * blockDim.x + threadIdx.x;   // over 1<<20
    int nn = idx >> 10;      // output col e  -> B row
    int kk = idx & 1023;     // input dim d   -> B col
    g_Bh[idx] = __float2half(w1[(kk << 10) + nn]);
}

// ---------------- kernel 3: query projection q[b][e] = dec[b]@w2 + b2 + b1 ----------------
__global__ void query_kernel(const float* __restrict__ dec,
                             const float* __restrict__ w2,
                             const float* __restrict__ b2,
                             const float* __restrict__ b1) {
    const int b = blockIdx.y;
    const int t = threadIdx.x;
    const int e = blockIdx.x * 256 + t;
    __shared__ float sd[EDIM];
    for (int i = t; i < EDIM; i += 256) sd[i] = dec[b * EDIM + i];
    __syncthreads();
    float acc = b2[e] + b1[e];
#pragma unroll 8
    for (int d = 0; d < EDIM; ++d) acc += sd[d] * w2[(d << 10) + e];
    g_q[b * EDIM + e] = acc;
}

// ---------------- kernel 4: pipelined fp16 GEMM + fused tanh·v -> scores ----------
#define LDSM4(R0, R1, R2, R3, addr)                                              \
    asm volatile("ldmatrix.sync.aligned.m8n8.x4.shared.b16 {%0,%1,%2,%3}, [%4];" \
                 : "=r"(R0), "=r"(R1), "=r"(R2), "=r"(R3) : "r"(addr))

#define MMA16816(d, a, b0r, b1r)                                                  \
    asm volatile("mma.sync.aligned.m16n8k16.row.col.f32.f16.f16.f32 "             \
                 "{%0,%1,%2,%3}, {%4,%5,%6,%7}, {%8,%9}, {%0,%1,%2,%3};"          \
                 : "+f"((d)[0]), "+f"((d)[1]), "+f"((d)[2]), "+f"((d)[3])         \
                 : "r"((a)[0]), "r"((a)[1]), "r"((a)[2]), "r"((a)[3]),            \
                   "r"(b0r), "r"(b1r))

#define CP_ASYNC16(dst, src)                                                     \
    asm volatile("cp.async.cg.shared.global [%0], [%1], 16;" :: "r"(dst), "l"(src))
#define CP_COMMIT() asm volatile("cp.async.commit_group;" ::: "memory")
#define CP_WAIT1()  asm volatile("cp.async.wait_group 1;" ::: "memory")

// Chunk = (np, k0): tiles {A 128x64h, B 128x64h}, 128-B rows, SW128 swizzle
// (phys = off ^ ((row & 7) << 4)).  3-stage ring.  128 chunks = 8 np * 16 k-chunks.
#define TILE_BYTES 16384
#define STG_BYTES  32768
#define OFF_Q   98304
#define OFF_V   102400
#define OFF_ACC 106496
#define SMEM_TOTAL 107008

__global__ void __launch_bounds__(256, 2) scores_kernel(const float* __restrict__ v) {
    extern __shared__ char smem[];
    uint32_t sb;
    asm("{ .reg .u64 t; cvta.to.shared.u64 t, %1; cvt.u32.u64 %0, t; }"
        : "=r"(sb) : "l"(smem));

    const int tid  = threadIdx.x;
    const int lane = tid & 31;
    const int wid  = tid >> 5;
    const int wm   = wid >> 1;   // 0..3
    const int wn   = wid & 1;    // 0..1
    const int row0 = blockIdx.x << 7;
    const int b    = row0 >> 11;

    float* s_q   = reinterpret_cast<float*>(smem + OFF_Q);
    float* s_v   = reinterpret_cast<float*>(smem + OFF_V);
    float* s_acc = reinterpret_cast<float*>(smem + OFF_ACC);

    for (int i = tid; i < EDIM; i += 256) {
        s_q[i] = g_q[(b << 10) + i];
        s_v[i] = v[i];
    }
    if (tid < 128) s_acc[tid] = 0.0f;

    // ---- ldmatrix addresses (SW128 swizzled, per-thread constants) ----
    // A: row = wm*32 + (lane&15); logical granule per kk: 2*kk + (lane>>4)
    const int row_a = wm * 32 + (lane & 15);
    const int ga    = lane >> 4;
    const int xa    = row_a & 7;
    uint32_t a_off[4];
#pragma unroll
    for (int kk = 0; kk < 4; ++kk)
        a_off[kk] = (uint32_t)(row_a * 128 + (((2 * kk + ga) ^ xa) << 4));
    // B: row = wn*64 + ((lane>>4)<<3) + (lane&7); granule per kk: 2*kk + ((lane>>3)&1)
    const int row_b = wn * 64 + ((lane >> 4) << 3) + (lane & 7);
    const int gb    = (lane >> 3) & 1;
    const int xb    = row_b & 7;
    uint32_t b_off[4];
#pragma unroll
    for (int kk = 0; kk < 4; ++kk)
        b_off[kk] = (uint32_t)(row_b * 128 + (((2 * kk + gb) ^ xb) << 4));

    // ---- staging: 1024 uint4 slots per tile, 4 per thread ----
    auto stage = [&](int it) {
        const int np = it >> 4;
        const int k0 = (it & 15) << 6;        // halves
        const uint32_t base = sb + (uint32_t)(it % 3) * STG_BYTES;
#pragma unroll
        for (int j = 0; j < 4; ++j) {
            const int i = tid + (j << 8);
            const int r = i >> 3, g = i & 7;
            const uint32_t doff = (uint32_t)(r * 128 + ((g ^ (r & 7)) << 4));
            CP_ASYNC16(base + doff,
                       g_Ah + (((size_t)(row0 + r)) << 10) + k0 + g * 8);
            CP_ASYNC16(base + TILE_BYTES + doff,
                       g_Bh + (((size_t)((np << 7) + r)) << 10) + k0 + g * 8);
        }
    };

    // prologue: prefetch 2 chunks
    stage(0); CP_COMMIT();
    stage(1); CP_COMMIT();

    float acc[16][4];

#pragma unroll 1
    for (int c = 0; c < 128; ++c) {
        if ((c & 15) == 0) {
#pragma unroll
            for (int i = 0; i < 16; ++i) {
                acc[i][0] = 0.f; acc[i][1] = 0.f; acc[i][2] = 0.f; acc[i][3] = 0.f;
            }
        }

        CP_WAIT1();          // chunk c resident
        __syncthreads();     // all warps done reading buffer (c-1)%3

        if (c + 2 < 128) stage(c + 2);   // overlaps the MMA body below
        CP_COMMIT();

        const uint32_t a_base = sb + (uint32_t)(c % 3) * STG_BYTES;
        const uint32_t b_base = a_base + TILE_BYTES;
#pragma unroll
        for (int kk = 0; kk < 4; ++kk) {
            uint32_t a0[4], a1[4];
            LDSM4(a0[0], a0[1], a0[2], a0[3], a_base + a_off[kk]);
            LDSM4(a1[0], a1[1], a1[2], a1[3], a_base + a_off[kk] + 2048);
#pragma unroll
            for (int p = 0; p < 4; ++p) {
                uint32_t bb0, bb1, bb2, bb3;
                LDSM4(bb0, bb1, bb2, bb3, b_base + b_off[kk] + p * 2048);
                MMA16816(acc[(p << 1)],         a0, bb0, bb1);
                MMA16816(acc[(p << 1) + 1],     a0, bb2, bb3);
                MMA16816(acc[8 + (p << 1)],     a1, bb0, bb1);
                MMA16816(acc[8 + (p << 1) + 1], a1, bb2, bb3);
            }
        }

        if ((c & 15) == 15) {
            // epilogue for n-chunk np: score_part[row] += sum_n tanh(C + q) * v
            const int np = c >> 4;
            float part[4] = {0.f, 0.f, 0.f, 0.f};
            const int ncol0 = (np << 7) + wn * 64 + ((lane & 3) << 1);
#pragma unroll
            for (int mf = 0; mf < 2; ++mf) {
#pragma unroll
                for (int nf = 0; nf < 8; ++nf) {
                    int n = ncol0 + (nf << 3);
                    float q0 = s_q[n], q1 = s_q[n + 1];
                    float v0 = s_v[n], v1 = s_v[n + 1];
                    const float* cc = acc[mf * 8 + nf];
                    part[mf * 2 + 0] += tanhf(cc[0] + q0) * v0 + tanhf(cc[1] + q1) * v1;
                    part[mf * 2 + 1] += tanhf(cc[2] + q0) * v0 + tanhf(cc[3] + q1) * v1;
                }
            }
            const int rb = wm * 32 + (lane >> 2);
            atomicAdd(&s_acc[rb],      part[0]);
            atomicAdd(&s_acc[rb + 8],  part[1]);
            atomicAdd(&s_acc[rb + 16], part[2]);
            atomicAdd(&s_acc[rb + 24], part[3]);
        }
    }

    __syncthreads();
    if (tid < 128) g_scores[row0 + tid] = s_acc[tid];   // +bv dropped: softmax-invariant
}

// ---------------- kernel 5: softmax over S per batch ----------------
__global__ void softmax_kernel() {
    const int b = blockIdx.x;
    const int t = threadIdx.x;
    __shared__ float red[256];
    const float* sc = g_scores + b * SEQ;
    float* at = g_attn + b * SEQ;

    float m = -1e30f;
    for (int i = t; i < SEQ; i += 256) m = fmaxf(m, sc[i]);
    red[t] = m; __syncthreads();
#pragma unroll
    for (int o = 128; o > 0; o >>= 1) {
        if (t < o) red[t] = fmaxf(red[t], red[t + o]);
        __syncthreads();
    }
    float mx = red[0];
    __syncthreads();

    float s = 0.f;
    for (int i = t; i < SEQ; i += 256) {
        float e = expf(sc[i] - mx);
        at[i] = e;
        s += e;
    }
    red[t] = s; __syncthreads();
#pragma unroll
    for (int o = 128; o > 0; o >>= 1) {
        if (t < o) red[t] += red[t + o];
        __syncthreads();
    }
    float inv = 1.0f / red[0];
    for (int i = t; i < SEQ; i += 256) at[i] *= inv;
}

// ---------------- kernel 6: context[b][e] = sum_s attn * enc ----------------
__global__ void context_kernel(const float* __restrict__ enc, float* __restrict__ out) {
    const int b = blockIdx.y;
    const int chunk = blockIdx.x;      // 4 chunks of 256 e
    const int t = threadIdx.x;
    const int sub = t >> 6;            // 4 s-partitions
    const int tt = t & 63;

    __shared__ float sa[SEQ];
    __shared__ float4 part[3][64];
    for (int i = t; i < SEQ; i += 256) sa[i] = g_attn[b * SEQ + i];
    __syncthreads();

    const float4* ep = reinterpret_cast<const float4*>(enc) +
                       (size_t)b * SEQ * 256 + chunk * 64 + tt;
    float4 acc = {0.f, 0.f, 0.f, 0.f};
    const int s0 = sub * 512;
#pragma unroll 8
    for (int s = s0; s < s0 + 512; ++s) {
        float a = sa[s];
        float4 x = ep[(size_t)s * 256];
        acc.x += a * x.x; acc.y += a * x.y; acc.z += a * x.z; acc.w += a * x.w;
    }
    if (sub) part[sub - 1][tt] = acc;
    __syncthreads();
    if (sub == 0) {
#pragma unroll
        for (int j = 0; j < 3; ++j) {
            float4 p = part[j][tt];
            acc.x += p.x; acc.y += p.y; acc.z += p.z; acc.w += p.w;
        }
        reinterpret_cast<float4*>(out)[b * 256 + chunk * 64 + tt] = acc;
    }
}

// ---------------- launch ----------------
extern "C" void kernel_launch(void* const* d_in, const int* in_sizes, int n_in,
                              void* d_out, int out_size) {
    const float* enc = (const float*)d_in[0];   // [32,2048,1024]
    const float* dec = (const float*)d_in[1];   // [32,1,1024]
    const float* w1  = (const float*)d_in[2];   // [1024,1024]
    const float* b1  = (const float*)d_in[3];   // [1024]
    const float* w2  = (const float*)d_in[4];   // [1024,1024]
    const float* b2  = (const float*)d_in[5];   // [1024]
    const float* v   = (const float*)d_in[6];   // [1024,1]
    // d_in[7] = bv: softmax-invariant, unused.
    float* out = (float*)d_out;                 // [32,1024]

    cudaFuncSetAttribute(scores_kernel,
                         cudaFuncAttributeMaxDynamicSharedMemorySize, SMEM_TOTAL);

    conv_enc_kernel<<<8192, 256>>>(enc);
    conv_w1_kernel<<<(EDIM * EDIM) / 256, 256>>>(w1);
    query_kernel<<<dim3(4, BATCH), 256>>>(dec, w2, b2, b1);
    scores_kernel<<<NROWS / 128, 256, SMEM_TOTAL>>>(v);
    softmax_kernel<<<BATCH, 256>>>();
    context_kernel<<<dim3(4, BATCH), 256>>>(enc, out);
}